// round 1
// baseline (speedup 1.0000x reference)
#include <cuda_runtime.h>
#include <cstdint>

// Problem constants (from reference_code)
constexpr int F     = 8;
constexpr int B     = 4096;
constexpr int L     = 20;
constexpr int BL    = B * L;        // 81920
constexpr int VOCAB = 1000000;
constexpr int DIM   = 128;          // 128 floats = 32 float4 per row
constexpr int ROWS  = F * BL;       // 655360 output rows

// perm for SPLIT_SIZES=(4,4), SPLIT_ORDER=(1,0): [4,5,6,7,0,1,2,3] == (f+4)&7

__global__ __launch_bounds__(256)
void emb_gather_kernel(const int* __restrict__ vals,
                       const float4* __restrict__ table,
                       float4* __restrict__ out)
{
    const int warp = (blockIdx.x * 256 + threadIdx.x) >> 5;   // one warp per row
    const int lane = threadIdx.x & 31;
    if (warp >= ROWS) return;

    const int f   = warp / BL;
    const int pos = warp - f * BL;
    const int src_f = (f + 4) & 7;          // feature-block permutation

    int id = 0;
    if (lane == 0) id = __ldg(&vals[src_f * BL + pos]);
    id = __shfl_sync(0xFFFFFFFFu, id, 0);

    const unsigned slot = (unsigned)id % (unsigned)VOCAB;

    // 512B coalesced row copy: 32 lanes x float4
    const float4 v = __ldg(&table[(size_t)slot * (DIM / 4) + lane]);
    out[(size_t)warp * (DIM / 4) + lane] = v;
}

extern "C" void kernel_launch(void* const* d_in, const int* in_sizes, int n_in,
                              void* d_out, int out_size)
{
    const int*    vals  = (const int*)d_in[0];     // [F, B*L] int32
    const float4* table = (const float4*)d_in[1];  // [VOCAB, DIM] float32
    float4*       out   = (float4*)d_out;          // [F, B*L, DIM] float32

    const int threads = 256;
    const int warps_per_block = threads / 32;
    const int blocks = (ROWS + warps_per_block - 1) / warps_per_block;  // 81920
    emb_gather_kernel<<<blocks, threads>>>(vals, table, out);
}

// round 2
// speedup vs baseline: 1.2529x; 1.2529x over previous
#include <cuda_runtime.h>
#include <cstdint>

// Problem constants (from reference_code)
constexpr int F     = 8;
constexpr int B     = 4096;
constexpr int L     = 20;
constexpr int BL    = B * L;        // 81920
constexpr int VOCAB = 1000000;
constexpr int DIM   = 128;          // 128 floats = 32 float4 per row
constexpr int ROWS  = F * BL;       // 655360 output rows
constexpr int R     = 4;            // rows per warp (BL % R == 0)

// perm for SPLIT_SIZES=(4,4), SPLIT_ORDER=(1,0): [4,5,6,7,0,1,2,3] == (f+4)&7

__global__ __launch_bounds__(256)
void emb_gather_kernel(const int* __restrict__ vals,
                       const float4* __restrict__ table,
                       float4* __restrict__ out)
{
    const int warp = (blockIdx.x * 256 + threadIdx.x) >> 5;
    const int lane = threadIdx.x & 31;

    const int base = warp * R;                 // first output row of this warp
    if (base >= ROWS) return;

    const int f   = base / BL;                 // all R rows share one feature
    const int pos = base - f * BL;
    const int src_f = (f + 4) & 7;             // feature-block permutation

    // lanes 0..R-1 fetch R consecutive ids (single 16B sector)
    int id = 0;
    if (lane < R) id = __ldg(&vals[src_f * BL + pos + lane]);

    unsigned slot[R];
    #pragma unroll
    for (int r = 0; r < R; r++)
        slot[r] = (unsigned)__shfl_sync(0xFFFFFFFFu, id, r) % (unsigned)VOCAB;

    // R independent 512B row loads in flight (MLP = R per warp)
    float4 v[R];
    #pragma unroll
    for (int r = 0; r < R; r++)
        v[r] = __ldg(&table[(size_t)slot[r] * (DIM / 4) + lane]);

    // streaming stores: evict-first, keep L2 for table rows
    #pragma unroll
    for (int r = 0; r < R; r++)
        __stcs(&out[(size_t)(base + r) * (DIM / 4) + lane], v[r]);
}

extern "C" void kernel_launch(void* const* d_in, const int* in_sizes, int n_in,
                              void* d_out, int out_size)
{
    const int*    vals  = (const int*)d_in[0];     // [F, B*L] int32
    const float4* table = (const float4*)d_in[1];  // [VOCAB, DIM] float32
    float4*       out   = (float4*)d_out;          // [F, B*L, DIM] float32

    const int threads = 256;
    const int rows_per_block = (threads / 32) * R; // 32
    const int blocks = (ROWS + rows_per_block - 1) / rows_per_block;  // 20480
    emb_gather_kernel<<<blocks, threads>>>(vals, table, out);
}